// round 9
// baseline (speedup 1.0000x reference)
#include <cuda_runtime.h>
#include <math.h>

#define NQ 4
#define SDIM 16
#define KCOLS 512
#define TPB 512
#define ROWS_PER_BLK 64

// One fused kernel: coalesced split-K GEMM (all 512 threads) + circuit epilogue
// (threads 0..63, one row each) overlapped across waves.
__global__ __launch_bounds__(TPB, 2) void qnet_fused_kernel(
    const float* __restrict__ A,       // [B,512]
    const float* __restrict__ pre_w,   // [4,512]
    const float* __restrict__ pre_b,   // [4]
    const float* __restrict__ u3p,     // [4,3]
    const float* __restrict__ post_w,  // [2,4]
    const float* __restrict__ post_b,  // [2]
    float* __restrict__ out,           // [B,2]
    int B)
{
    // Permuted weight layout: entry for column c lives at
    //   idx = colLane + 8*k + 32*j,  cq=c>>2, k=c&3, colLane=cq&7, j=cq>>3
    // -> conflict-free LDS.128 with 4-row broadcast at every step j.
    __shared__ float4 wsm[KCOLS];
    __shared__ float4 preS[ROWS_PER_BLK];
    __shared__ float  g[NQ][8];        // u3 gates {g00, g01r,g01i, g10r,g10i, g11r,g11i, pad}

    const int tid = threadIdx.x;

    // Stage weights (one column per thread, permuted)
    {
        const int c = tid;
        const int cq = c >> 2, k = c & 3;
        const int idx = (cq & 7) + 8 * k + 32 * (cq >> 3);
        wsm[idx] = make_float4(pre_w[c],
                               pre_w[KCOLS + c],
                               pre_w[2 * KCOLS + c],
                               pre_w[3 * KCOLS + c]);
    }
    // Batch-independent U3 gates
    if (tid < NQ) {
        const int q = tid;
        float th = u3p[q * 3 + 0], ph = u3p[q * 3 + 1], la = u3p[q * 3 + 2];
        float ct, st, cl, sl, cp, sp;
        sincosf(0.5f * th, &st, &ct);
        sincosf(la, &sl, &cl);
        sincosf(ph, &sp, &cp);
        float cpl = cp * cl - sp * sl;
        float spl = sp * cl + cp * sl;
        g[q][0] = ct;
        g[q][1] = -cl * st;  g[q][2] = -sl * st;
        g[q][3] =  cp * st;  g[q][4] =  sp * st;
        g[q][5] =  cpl * ct; g[q][6] =  spl * ct;
        g[q][7] = 0.0f;
    }
    __syncthreads();

    // ================= Phase A: split-K GEMM (all 512 threads) =================
    const int warp = tid >> 5;
    const int lane = tid & 31;
    const int colLane  = lane & 7;          // position within 8-lane row-team
    const int rowInWrp = lane >> 3;         // 0..3
    const int row = blockIdx.x * ROWS_PER_BLK + warp * 4 + rowInWrp;

    float a0 = 0.f, a1 = 0.f, a2 = 0.f, a3 = 0.f;
    if (row < B) {
        const float4* rp = (const float4*)(A + (size_t)row * KCOLS);
        #pragma unroll
        for (int j = 0; j < 16; j++) {
            float4 x = rp[colLane + 8 * j];           // warp: 4 full 128B lines
            const float4* wj = &wsm[32 * j + colLane];
            float4 w0 = wj[0];
            float4 w1 = wj[8];
            float4 w2 = wj[16];
            float4 w3 = wj[24];
            a0 += x.x * w0.x + x.y * w1.x + x.z * w2.x + x.w * w3.x;
            a1 += x.x * w0.y + x.y * w1.y + x.z * w2.y + x.w * w3.y;
            a2 += x.x * w0.z + x.y * w1.z + x.z * w2.z + x.w * w3.z;
            a3 += x.x * w0.w + x.y * w1.w + x.z * w2.w + x.w * w3.w;
        }
    }
    #pragma unroll
    for (int off = 4; off; off >>= 1) {
        a0 += __shfl_xor_sync(0xffffffffu, a0, off);
        a1 += __shfl_xor_sync(0xffffffffu, a1, off);
        a2 += __shfl_xor_sync(0xffffffffu, a2, off);
        a3 += __shfl_xor_sync(0xffffffffu, a3, off);
    }
    if (colLane == 0)
        preS[warp * 4 + rowInWrp] = make_float4(a0 + pre_b[0], a1 + pre_b[1],
                                                a2 + pre_b[2], a3 + pre_b[3]);
    __syncthreads();

    // ================= Phase B: circuit epilogue (threads 0..63) =================
    if (tid >= ROWS_PER_BLK) return;
    const int b = blockIdx.x * ROWS_PER_BLK + tid;
    if (b >= B) return;

    float4 p4 = preS[tid];
    float pre[NQ] = {p4.x, p4.y, p4.z, p4.w};

    float ryc[NQ], rys[NQ], rzc[NQ], rzs[NQ];
    #pragma unroll
    for (int q = 0; q < NQ; q++) {
        float t  = tanhf(pre[q] * 0.1f) * 1.5707963267948966f;
        float ry = atanf(t);
        float rz = atanf(t * t);
        __sincosf(0.5f * ry, &rys[q], &ryc[q]);
        __sincosf(0.5f * rz, &rzs[q], &rzc[q]);
    }

    float re[SDIM], im[SDIM];
    #pragma unroll
    for (int i = 0; i < SDIM; i++) { re[i] = 0.25f; im[i] = 0.0f; }

    // RY layer (state stays real)
    #pragma unroll
    for (int q = 0; q < NQ; q++) {
        const int bit = 8 >> q;
        const float c = ryc[q], s = rys[q];
        #pragma unroll
        for (int i = 0; i < SDIM; i++) {
            if (!(i & bit)) {
                float r0 = re[i], r1 = re[i | bit];
                re[i]       = c * r0 - s * r1;
                re[i | bit] = s * r0 + c * r1;
            }
        }
    }

    // RZ layer
    #pragma unroll
    for (int q = 0; q < NQ; q++) {
        const int bit = 8 >> q;
        const float c = rzc[q], sz = rzs[q];
        #pragma unroll
        for (int i = 0; i < SDIM; i++) {
            float s = (i & bit) ? sz : -sz;
            float r = re[i], m = im[i];
            re[i] = r * c - m * s;
            im[i] = r * s + m * c;
        }
    }

    // CNOT rings (register permutations)
    #define CNOT_(cq, tq)                                                  \
    {                                                                      \
        const int bc = 8 >> (cq), bt = 8 >> (tq);                          \
        _Pragma("unroll")                                                  \
        for (int i = 0; i < SDIM; i++) {                                   \
            if ((i & bc) && !(i & bt)) {                                   \
                float tr = re[i]; re[i] = re[i | bt]; re[i | bt] = tr;     \
                float tm = im[i]; im[i] = im[i | bt]; im[i | bt] = tm;     \
            }                                                              \
        }                                                                  \
    }
    CNOT_(0, 1); CNOT_(1, 2); CNOT_(2, 3); CNOT_(3, 0);
    CNOT_(0, 2); CNOT_(1, 3); CNOT_(2, 0); CNOT_(3, 1);
    #undef CNOT_

    // U3 layer
    #pragma unroll
    for (int q = 0; q < NQ; q++) {
        const int bit = 8 >> q;
        const float g00  = g[q][0];
        const float g01r = g[q][1], g01i = g[q][2];
        const float g10r = g[q][3], g10i = g[q][4];
        const float g11r = g[q][5], g11i = g[q][6];
        #pragma unroll
        for (int i = 0; i < SDIM; i++) {
            if (!(i & bit)) {
                const int j = i | bit;
                float r0 = re[i], m0 = im[i], r1 = re[j], m1 = im[j];
                re[i] = g00 * r0 + g01r * r1 - g01i * m1;
                im[i] = g00 * m0 + g01r * m1 + g01i * r1;
                re[j] = g10r * r0 - g10i * m0 + g11r * r1 - g11i * m1;
                im[j] = g10r * m0 + g10i * r0 + g11r * m1 + g11i * r1;
            }
        }
    }

    // Z expectations
    float e0 = 0.f, e1 = 0.f, e2 = 0.f, e3 = 0.f;
    #pragma unroll
    for (int i = 0; i < SDIM; i++) {
        float p = re[i] * re[i] + im[i] * im[i];
        e0 += (i & 8) ? -p : p;
        e1 += (i & 4) ? -p : p;
        e2 += (i & 2) ? -p : p;
        e3 += (i & 1) ? -p : p;
    }

    float o0 = post_b[0] + e0 * post_w[0] + e1 * post_w[1] + e2 * post_w[2] + e3 * post_w[3];
    float o1 = post_b[1] + e0 * post_w[4] + e1 * post_w[5] + e2 * post_w[6] + e3 * post_w[7];
    ((float2*)out)[b] = make_float2(o0, o1);
}

extern "C" void kernel_launch(void* const* d_in, const int* in_sizes, int n_in,
                              void* d_out, int out_size) {
    const float* A      = (const float*)d_in[0];   // input_features [B,512]
    const float* pre_w  = (const float*)d_in[1];   // [4,512]
    const float* pre_b  = (const float*)d_in[2];   // [4]
    const float* u3p    = (const float*)d_in[3];   // [4,3]
    const float* post_w = (const float*)d_in[4];   // [2,4]
    const float* post_b = (const float*)d_in[5];   // [2]
    float* out          = (float*)d_out;           // [B,2]

    const int B = in_sizes[0] / KCOLS;
    const int grid = (B + ROWS_PER_BLK - 1) / ROWS_PER_BLK;
    qnet_fused_kernel<<<grid, TPB>>>(A, pre_w, pre_b, u3p, post_w, post_b, out, B);
}

// round 10
// speedup vs baseline: 1.1064x; 1.1064x over previous
#include <cuda_runtime.h>
#include <math.h>

#define NQ 4
#define SDIM 16
#define KCOLS 512
#define TPB 256
#define ROWS_PER_BLK 32    // 8 warps x 4 rows/warp

// Fused: coalesced split-K GEMM with front-batched loads (high MLP) + circuit
// epilogue on threads 0..31. launch_bounds(256,2) -> up to 128 regs/thread.
__global__ __launch_bounds__(TPB, 2) void qnet_fused_kernel(
    const float* __restrict__ A,       // [B,512]
    const float* __restrict__ pre_w,   // [4,512]
    const float* __restrict__ pre_b,   // [4]
    const float* __restrict__ u3p,     // [4,3]
    const float* __restrict__ post_w,  // [2,4]
    const float* __restrict__ post_b,  // [2]
    float* __restrict__ out,           // [B,2]
    int B)
{
    // Permuted weight layout: column c -> idx = colLane + 8*k + 32*j
    // (cq=c>>2, k=c&3, colLane=cq&7, j=cq>>3): conflict-free broadcast LDS.128.
    __shared__ float4 wsm[KCOLS];
    __shared__ float4 preS[ROWS_PER_BLK];
    __shared__ float  g[NQ][8];

    const int tid = threadIdx.x;

    // Stage weights (2 columns per thread, permuted)
    #pragma unroll
    for (int t = 0; t < 2; t++) {
        const int c = tid + t * TPB;
        const int cq = c >> 2, k = c & 3;
        const int idx = (cq & 7) + 8 * k + 32 * (cq >> 3);
        wsm[idx] = make_float4(pre_w[c],
                               pre_w[KCOLS + c],
                               pre_w[2 * KCOLS + c],
                               pre_w[3 * KCOLS + c]);
    }
    // Batch-independent U3 gates
    if (tid < NQ) {
        const int q = tid;
        float th = u3p[q * 3 + 0], ph = u3p[q * 3 + 1], la = u3p[q * 3 + 2];
        float ct, st, cl, sl, cp, sp;
        sincosf(0.5f * th, &st, &ct);
        sincosf(la, &sl, &cl);
        sincosf(ph, &sp, &cp);
        float cpl = cp * cl - sp * sl;
        float spl = sp * cl + cp * sl;
        g[q][0] = ct;
        g[q][1] = -cl * st;  g[q][2] = -sl * st;
        g[q][3] =  cp * st;  g[q][4] =  sp * st;
        g[q][5] =  cpl * ct; g[q][6] =  spl * ct;
        g[q][7] = 0.0f;
    }
    __syncthreads();

    // ================= Phase A: GEMM, front-batched loads =================
    const int warp = tid >> 5;
    const int lane = tid & 31;
    const int colLane  = lane & 7;          // 8-lane team per row
    const int rowInWrp = lane >> 3;         // 0..3
    const int row = blockIdx.x * ROWS_PER_BLK + warp * 4 + rowInWrp;

    // Batch ALL 16 row loads first: 16 independent LDG.128 in flight per thread.
    float4 x[16];
    {
        const float4* rp = (const float4*)(A + (size_t)row * KCOLS);
        #pragma unroll
        for (int j = 0; j < 16; j++)
            x[j] = rp[colLane + 8 * j];      // warp: 4 full 128B lines each
    }

    float a0 = 0.f, a1 = 0.f, a2 = 0.f, a3 = 0.f;
    #pragma unroll
    for (int j = 0; j < 16; j++) {
        const float4* wj = &wsm[32 * j + colLane];
        float4 w0 = wj[0];
        float4 w1 = wj[8];
        float4 w2 = wj[16];
        float4 w3 = wj[24];
        a0 += x[j].x * w0.x + x[j].y * w1.x + x[j].z * w2.x + x[j].w * w3.x;
        a1 += x[j].x * w0.y + x[j].y * w1.y + x[j].z * w2.y + x[j].w * w3.y;
        a2 += x[j].x * w0.z + x[j].y * w1.z + x[j].z * w2.z + x[j].w * w3.z;
        a3 += x[j].x * w0.w + x[j].y * w1.w + x[j].z * w2.w + x[j].w * w3.w;
    }
    #pragma unroll
    for (int off = 4; off; off >>= 1) {
        a0 += __shfl_xor_sync(0xffffffffu, a0, off);
        a1 += __shfl_xor_sync(0xffffffffu, a1, off);
        a2 += __shfl_xor_sync(0xffffffffu, a2, off);
        a3 += __shfl_xor_sync(0xffffffffu, a3, off);
    }
    if (colLane == 0)
        preS[warp * 4 + rowInWrp] = make_float4(a0 + pre_b[0], a1 + pre_b[1],
                                                a2 + pre_b[2], a3 + pre_b[3]);
    __syncthreads();

    // ================= Phase B: circuit epilogue (threads 0..31) =================
    if (tid >= ROWS_PER_BLK) return;
    const int b = blockIdx.x * ROWS_PER_BLK + tid;
    if (b >= B) return;

    float4 p4 = preS[tid];
    float pre[NQ] = {p4.x, p4.y, p4.z, p4.w};

    float ryc[NQ], rys[NQ], rzc[NQ], rzs[NQ];
    #pragma unroll
    for (int q = 0; q < NQ; q++) {
        float t  = tanhf(pre[q] * 0.1f) * 1.5707963267948966f;
        float ry = atanf(t);
        float rz = atanf(t * t);
        __sincosf(0.5f * ry, &rys[q], &ryc[q]);
        __sincosf(0.5f * rz, &rzs[q], &rzc[q]);
    }

    float re[SDIM], im[SDIM];
    #pragma unroll
    for (int i = 0; i < SDIM; i++) { re[i] = 0.25f; im[i] = 0.0f; }

    // RY layer (state stays real)
    #pragma unroll
    for (int q = 0; q < NQ; q++) {
        const int bit = 8 >> q;
        const float c = ryc[q], s = rys[q];
        #pragma unroll
        for (int i = 0; i < SDIM; i++) {
            if (!(i & bit)) {
                float r0 = re[i], r1 = re[i | bit];
                re[i]       = c * r0 - s * r1;
                re[i | bit] = s * r0 + c * r1;
            }
        }
    }

    // RZ layer
    #pragma unroll
    for (int q = 0; q < NQ; q++) {
        const int bit = 8 >> q;
        const float c = rzc[q], sz = rzs[q];
        #pragma unroll
        for (int i = 0; i < SDIM; i++) {
            float s = (i & bit) ? sz : -sz;
            float r = re[i], m = im[i];
            re[i] = r * c - m * s;
            im[i] = r * s + m * c;
        }
    }

    // CNOT rings (register permutations)
    #define CNOT_(cq, tq)                                                  \
    {                                                                      \
        const int bc = 8 >> (cq), bt = 8 >> (tq);                          \
        _Pragma("unroll")                                                  \
        for (int i = 0; i < SDIM; i++) {                                   \
            if ((i & bc) && !(i & bt)) {                                   \
                float tr = re[i]; re[i] = re[i | bt]; re[i | bt] = tr;     \
                float tm = im[i]; im[i] = im[i | bt]; im[i | bt] = tm;     \
            }                                                              \
        }                                                                  \
    }
    CNOT_(0, 1); CNOT_(1, 2); CNOT_(2, 3); CNOT_(3, 0);
    CNOT_(0, 2); CNOT_(1, 3); CNOT_(2, 0); CNOT_(3, 1);
    #undef CNOT_

    // U3 layer
    #pragma unroll
    for (int q = 0; q < NQ; q++) {
        const int bit = 8 >> q;
        const float g00  = g[q][0];
        const float g01r = g[q][1], g01i = g[q][2];
        const float g10r = g[q][3], g10i = g[q][4];
        const float g11r = g[q][5], g11i = g[q][6];
        #pragma unroll
        for (int i = 0; i < SDIM; i++) {
            if (!(i & bit)) {
                const int j = i | bit;
                float r0 = re[i], m0 = im[i], r1 = re[j], m1 = im[j];
                re[i] = g00 * r0 + g01r * r1 - g01i * m1;
                im[i] = g00 * m0 + g01r * m1 + g01i * r1;
                re[j] = g10r * r0 - g10i * m0 + g11r * r1 - g11i * m1;
                im[j] = g10r * m0 + g10i * r0 + g11r * m1 + g11i * r1;
            }
        }
    }

    // Z expectations
    float e0 = 0.f, e1 = 0.f, e2 = 0.f, e3 = 0.f;
    #pragma unroll
    for (int i = 0; i < SDIM; i++) {
        float p = re[i] * re[i] + im[i] * im[i];
        e0 += (i & 8) ? -p : p;
        e1 += (i & 4) ? -p : p;
        e2 += (i & 2) ? -p : p;
        e3 += (i & 1) ? -p : p;
    }

    float o0 = post_b[0] + e0 * post_w[0] + e1 * post_w[1] + e2 * post_w[2] + e3 * post_w[3];
    float o1 = post_b[1] + e0 * post_w[4] + e1 * post_w[5] + e2 * post_w[6] + e3 * post_w[7];
    ((float2*)out)[b] = make_float2(o0, o1);
}

extern "C" void kernel_launch(void* const* d_in, const int* in_sizes, int n_in,
                              void* d_out, int out_size) {
    const float* A      = (const float*)d_in[0];   // input_features [B,512]
    const float* pre_w  = (const float*)d_in[1];   // [4,512]
    const float* pre_b  = (const float*)d_in[2];   // [4]
    const float* u3p    = (const float*)d_in[3];   // [4,3]
    const float* post_w = (const float*)d_in[4];   // [2,4]
    const float* post_b = (const float*)d_in[5];   // [2]
    float* out          = (float*)d_out;           // [B,2]

    const int B = in_sizes[0] / KCOLS;
    const int grid = (B + ROWS_PER_BLK - 1) / ROWS_PER_BLK;   // 1024
    qnet_fused_kernel<<<grid, TPB>>>(A, pre_w, pre_b, u3p, post_w, post_b, out, B);
}